// round 15
// baseline (speedup 1.0000x reference)
#include <cuda_runtime.h>
#include <cuda_fp16.h>
#include <cstdint>

static constexpr int NE_MAX = 32768;
static constexpr int KC = 19;
static constexpr int CH = 128;
static constexpr int AW = 2432;

// weight segment offsets inside g_Whi/g_Wlo (elements)
static constexpr int W_FC0 = 0;                 // 640*640
static constexpr int W_FC1 = 409600;            // 512*512
static constexpr int W_FC2 = 671744;            // 384*384
static constexpr int W_W3  = 819200;            // 1536*128
static constexpr int W_TOT = 1015808;

// ------------------------- device scratch (no allocs allowed) ---------------
__device__ __align__(16) __half g_h2hi[(size_t)NE_MAX * CH];
__device__ __align__(16) __half g_h2lo[(size_t)NE_MAX * CH];
__device__ __align__(16) __half g_Ahi[(size_t)NE_MAX * AW];
__device__ __align__(16) __half g_Whi[W_TOT];
__device__ __align__(16) __half g_Wlo[W_TOT];

// A-block -> x source row (m-major expanded layout)
__constant__ int c_xrow[19] = {0,2,6,11,16, 3,7,12,17, 1,5,10,15, 8,13,18, 4,9,14};

// per-output-block GEMM config
struct Cfg { int acol0, K, wrow, col0, biasc, p0, p1, p2; };
__constant__ Cfg c_cfg[31] = {
  // --- SO2: fc0 (m=0), K=640, bias ---
  {0,    640, 0,      0,    0,   0,0,0},
  {0,    640, 81920,  256,  128, 0,0,0},
  {0,    640, 163840, 768,  256, 0,0,0},
  {0,    640, 245760, 1408, 384, 0,0,0},
  {0,    640, 327680, 2048, 512, 0,0,0},
  // --- fc1, +m rows {3,7,12,17} ---
  {640,  512, 409600, 384,  -1, 0,0,0},
  {640,  512, 475136, 896,  -1, 0,0,0},
  {640,  512, 540672, 1536, -1, 0,0,0},
  {640,  512, 606208, 2176, -1, 0,0,0},
  // --- fc1, -m rows {1,5,10,15} ---
  {1152, 512, 409600, 128,  -1, 0,0,0},
  {1152, 512, 475136, 640,  -1, 0,0,0},
  {1152, 512, 540672, 1280, -1, 0,0,0},
  {1152, 512, 606208, 1920, -1, 0,0,0},
  // --- fc2, +m rows {8,13,18} ---
  {1664, 384, 671744, 1024, -1, 0,0,0},
  {1664, 384, 720896, 1664, -1, 0,0,0},
  {1664, 384, 770048, 2304, -1, 0,0,0},
  // --- fc2, -m rows {4,9,14} ---
  {2048, 384, 671744, 512,  -1, 0,0,0},
  {2048, 384, 720896, 1152, -1, 0,0,0},
  {2048, 384, 770048, 1792, -1, 0,0,0},
  // --- w3 (radial layer 3), 12 blocks, K=128, bias=rb3, fused FiLM+split ---
  {0, 128, 819200,  0,    0,    0,0,0},
  {0, 128, 835584,  128,  128,  0,0,0},
  {0, 128, 851968,  256,  256,  0,0,0},
  {0, 128, 868352,  384,  384,  0,0,0},
  {0, 128, 884736,  512,  512,  0,0,0},
  {0, 128, 901120,  640,  640,  0,0,0},
  {0, 128, 917504,  768,  768,  0,0,0},
  {0, 128, 933888,  896,  896,  0,0,0},
  {0, 128, 950272,  1024, 1024, 0,0,0},
  {0, 128, 966656,  1152, 1152, 0,0,0},
  {0, 128, 983040,  1280, 1280, 0,0,0},
  {0, 128, 999424,  1408, 1408, 0,0,0},
};

// ------------------------- helpers ------------------------------------------
__device__ __forceinline__ uint32_t smem_u32(const void* p) {
  uint32_t a;
  asm("{ .reg .u64 t; cvta.to.shared.u64 t, %1; cvt.u32.u64 %0, t; }"
      : "=r"(a) : "l"(p));
  return a;
}
__device__ __forceinline__ void cp16(uint32_t dst, const void* src) {
  asm volatile("cp.async.cg.shared.global [%0], [%1], 16;" :: "r"(dst), "l"(src));
}
__device__ __forceinline__ void cp_commit() {
  asm volatile("cp.async.commit_group;");
}
__device__ __forceinline__ void cp_wait0() {
  asm volatile("cp.async.wait_group 0;" ::: "memory");
}
__device__ __forceinline__ void ldsm4(uint32_t* r, uint32_t a) {
  asm volatile("ldmatrix.sync.aligned.m8n8.x4.shared.b16 {%0,%1,%2,%3}, [%4];"
               : "=r"(r[0]), "=r"(r[1]), "=r"(r[2]), "=r"(r[3]) : "r"(a));
}
__device__ __forceinline__ void mma16816(float* c, const uint32_t* a,
                                         uint32_t b0, uint32_t b1) {
  asm volatile(
      "mma.sync.aligned.m16n8k16.row.col.f32.f16.f16.f32 "
      "{%0,%1,%2,%3}, {%4,%5,%6,%7}, {%8,%9}, {%0,%1,%2,%3};"
      : "+f"(c[0]), "+f"(c[1]), "+f"(c[2]), "+f"(c[3])
      : "r"(a[0]), "r"(a[1]), "r"(a[2]), "r"(a[3]), "r"(b0), "r"(b1));
}
__device__ __forceinline__ void split2(float v, __half& h, __half& l) {
  h = __float2half(v);
  l = __float2half(v - __half2float(h));
}

// ---- 3-term (mode1) smem layout: AH 0, AL 10240, WH 20480, WL 30720 ----
static constexpr int T_AL = 10240, T_WH = 20480, T_WL = 30720;
static constexpr int BUFB3 = 40960;
// ---- 1-term (mode0) compact layout: AH 0, WH 10240; K=64 super-chunks ----
static constexpr int OFF_W1 = 10240;
static constexpr int CH1B   = 20480;            // one 32-K sub-chunk
static constexpr int SBUF1  = 2 * CH1B;         // one 64-K super-chunk buffer
static constexpr int SMEM_G = 2 * SBUF1;        // 81920 (same for both modes)

// ============================================================================
// Unified GEMM (fp16 operands, fp32 accum):
//   mode 0 (SO2): D = Ah@Wh, K=64 super-chunk pipeline (halved sync overhead)
//   mode 1 (w3):  D = Ah@Wh + Ah@Wl + Al@Wh (3 terms, K=32 chunks), then
//                 fused epilogue: rad = D + bias; A = x_gather*rad -> fp16.
// 256 threads, 2 CTAs/SM, warp tile 32x64, M=128 CTA tile.
// ============================================================================
struct GemmCtx {
  const __half *gah, *gal, *gwh, *gwl;
  uint32_t sdst, sb;
  int arow, akoff, brow0, bkoff;
};

// ---------------- 1-term path (mode 0) ----------------
__device__ __forceinline__ void stage1(const GemmCtx& c, int kc, uint32_t bo) {
  const __half* p;
  p = c.gah + kc * 32; cp16(c.sdst + bo, p);           cp16(c.sdst + bo + 16, p + 8);
  p = c.gwh + kc * 32; cp16(c.sdst + bo + OFF_W1, p);  cp16(c.sdst + bo + OFF_W1 + 16, p + 8);
}

__device__ __forceinline__ void compute1(const GemmCtx& c, uint32_t bo,
                                         float acc[2][8][4]) {
#pragma unroll
  for (int ks = 0; ks < 2; ++ks) {
    uint32_t Ah[2][4];
#pragma unroll
    for (int m = 0; m < 2; ++m)
      ldsm4(Ah[m], c.sb + bo + (uint32_t)(c.arow + m * 16) * 80 + c.akoff + ks * 32);
#pragma unroll
    for (int n2 = 0; n2 < 4; ++n2) {
      uint32_t Bh[4];
      ldsm4(Bh, c.sb + bo + OFF_W1 +
                (uint32_t)(c.brow0 + n2 * 16) * 80 + c.bkoff + ks * 32);
      mma16816(acc[0][2 * n2],     Ah[0], Bh[0], Bh[1]);
      mma16816(acc[1][2 * n2],     Ah[1], Bh[0], Bh[1]);
      mma16816(acc[0][2 * n2 + 1], Ah[0], Bh[2], Bh[3]);
      mma16816(acc[1][2 * n2 + 1], Ah[1], Bh[2], Bh[3]);
    }
  }
}

template <int NSC>   // number of K=64 super-chunks
__device__ __forceinline__ void gemm_loop1(const GemmCtx& c, float acc[2][8][4]) {
  stage1(c, 0, 0);
  stage1(c, 1, CH1B);
  cp_commit();
  cp_wait0();
  __syncthreads();
#pragma unroll
  for (int sc = 0; sc < NSC; ++sc) {
    const uint32_t bo = (uint32_t)(sc & 1) * SBUF1;
    if (sc + 1 < NSC) {
      stage1(c, 2 * sc + 2, bo ^ SBUF1);
      stage1(c, 2 * sc + 3, (bo ^ SBUF1) + CH1B);
      cp_commit();
    }
    compute1(c, bo, acc);
    compute1(c, bo + CH1B, acc);
    if (sc + 1 < NSC) {
      cp_wait0();
      __syncthreads();
    }
  }
}

// ---------------- 3-term path (mode 1) ----------------
__device__ __forceinline__ void stage3(const GemmCtx& c, int kc, uint32_t bo) {
  const __half* p;
  p = c.gah + kc * 32; cp16(c.sdst + bo, p);          cp16(c.sdst + bo + 16, p + 8);
  p = c.gal + kc * 32; cp16(c.sdst + bo + T_AL, p);   cp16(c.sdst + bo + T_AL + 16, p + 8);
  p = c.gwh + kc * 32; cp16(c.sdst + bo + T_WH, p);   cp16(c.sdst + bo + T_WH + 16, p + 8);
  p = c.gwl + kc * 32; cp16(c.sdst + bo + T_WL, p);   cp16(c.sdst + bo + T_WL + 16, p + 8);
}

__device__ __forceinline__ void compute3(const GemmCtx& c, uint32_t bo,
                                         float acc[2][8][4]) {
#pragma unroll
  for (int ks = 0; ks < 2; ++ks) {
    uint32_t Ah[2][4], Al[2][4];
#pragma unroll
    for (int m = 0; m < 2; ++m) {
      const uint32_t aa =
          c.sb + bo + (uint32_t)(c.arow + m * 16) * 80 + c.akoff + ks * 32;
      ldsm4(Ah[m], aa);
      ldsm4(Al[m], aa + T_AL);
    }
#pragma unroll
    for (int n2 = 0; n2 < 4; ++n2) {
      const uint32_t ba =
          c.sb + bo + T_WH + (uint32_t)(c.brow0 + n2 * 16) * 80 + c.bkoff + ks * 32;
      uint32_t Bh[4], Bl[4];
      ldsm4(Bh, ba);
      ldsm4(Bl, ba + 10240);
      mma16816(acc[0][2 * n2],     Ah[0], Bh[0], Bh[1]);
      mma16816(acc[1][2 * n2],     Ah[1], Bh[0], Bh[1]);
      mma16816(acc[0][2 * n2 + 1], Ah[0], Bh[2], Bh[3]);
      mma16816(acc[1][2 * n2 + 1], Ah[1], Bh[2], Bh[3]);
      mma16816(acc[0][2 * n2],     Ah[0], Bl[0], Bl[1]);
      mma16816(acc[1][2 * n2],     Ah[1], Bl[0], Bl[1]);
      mma16816(acc[0][2 * n2 + 1], Ah[0], Bl[2], Bl[3]);
      mma16816(acc[1][2 * n2 + 1], Ah[1], Bl[2], Bl[3]);
      mma16816(acc[0][2 * n2],     Al[0], Bh[0], Bh[1]);
      mma16816(acc[1][2 * n2],     Al[1], Bh[0], Bh[1]);
      mma16816(acc[0][2 * n2 + 1], Al[0], Bh[2], Bh[3]);
      mma16816(acc[1][2 * n2 + 1], Al[1], Bh[2], Bh[3]);
    }
  }
}

__device__ __forceinline__ void gemm_loop3(const GemmCtx& c, float acc[2][8][4]) {
  stage3(c, 0, 0);
  cp_commit();
  cp_wait0();
  __syncthreads();
#pragma unroll
  for (int kc = 0; kc < 4; ++kc) {
    const uint32_t bo = (uint32_t)(kc & 1) * BUFB3;
    if (kc + 1 < 4) {
      stage3(c, kc + 1, bo ^ BUFB3);
      cp_commit();
    }
    compute3(c, bo, acc);
    if (kc + 1 < 4) {
      cp_wait0();
      __syncthreads();
    }
  }
}

__global__ void __launch_bounds__(256, 2)
mma_gemm(int mode, const float* __restrict__ bias,
         const float* __restrict__ xg,
         float* __restrict__ outp, int ostride, int cfg0)
{
  extern __shared__ char sm[];
  const Cfg cfg = c_cfg[cfg0 + blockIdx.x];
  const int K = cfg.K;
  const int t = threadIdx.x;
  const size_t e0 = (size_t)blockIdx.y * 128;

  // device-side A operand selection (device symbols invalid from host!)
  const __half* __restrict__ Ahi = (mode == 1) ? g_h2hi : g_Ahi;
  const __half* __restrict__ Alo = (mode == 1) ? g_h2lo : g_Ahi;  // unused mode0
  const int astride = (mode == 1) ? 128 : AW;

  GemmCtx c;
  c.sb = smem_u32(sm);

  // ---- staging mapping: 2 threads per row, 32 B (16 elems) per thread ----
  const int srow = t >> 1, sh = t & 1;
  c.gah = Ahi + (e0 + srow) * (size_t)astride + cfg.acol0 + sh * 16;
  c.gal = Alo + (e0 + srow) * (size_t)astride + cfg.acol0 + sh * 16;
  c.gwh = g_Whi + cfg.wrow + (size_t)srow * K + sh * 16;
  c.gwl = g_Wlo + cfg.wrow + (size_t)srow * K + sh * 16;
  c.sdst = c.sb + srow * 80 + sh * 32;

  // ---- compute mapping: 8 warps as 4 (rows) x 2 (cols); tile 32x64 ----
  const int wid = t >> 5, lane = t & 31;
  const int wr = wid & 3, wc = wid >> 2;
  const int lm = lane >> 3, lr = lane & 7;        // ldmatrix matrix id, row
  c.arow  = wr * 32 + ((lm & 1) ? 8 : 0) + lr;
  c.akoff = (lm & 2) ? 16 : 0;
  c.brow0 = wc * 64 + ((lm & 2) ? 8 : 0) + lr;
  c.bkoff = (lm & 1) ? 16 : 0;
  const int gq = lane >> 2, tg = lane & 3;

  float acc[2][8][4];
#pragma unroll
  for (int m = 0; m < 2; ++m)
#pragma unroll
    for (int n = 0; n < 8; ++n)
#pragma unroll
      for (int u = 0; u < 4; ++u) acc[m][n][u] = 0.f;

  if (mode == 1) {
    gemm_loop3(c, acc);               // w3: K=128, 3 terms (rad near-exact)
  } else {
    switch (K >> 6) {                 // SO2: 1 term, K=64 super-chunks
      case 6:  gemm_loop1<6>(c, acc);  break;
      case 8:  gemm_loop1<8>(c, acc);  break;
      default: gemm_loop1<10>(c, acc); break;
    }
  }

  if (mode == 1) {
    // ---- fused epilogue: rad = D + bias; A = x_gather * rad -> fp16 ----
    const int jb = blockIdx.x;                    // 0..11 rad block
    int tb0, tb1;
    if (jb < 5)      { tb0 = jb;     tb1 = -1;     }   // m = 0
    else if (jb < 9) { tb0 = jb;     tb1 = jb + 4; }   // m = 1 (+m, -m)
    else             { tb0 = jb + 4; tb1 = jb + 7; }   // m = 2 (+m, -m)
    const float* bp = bias + cfg.biasc;
#pragma unroll
    for (int m = 0; m < 2; ++m) {
#pragma unroll
      for (int n = 0; n < 8; ++n) {
        const int col = wc * 64 + n * 8 + tg * 2;
        const float b0v = bp[col], b1v = bp[col + 1];
        const size_t r0 = e0 + wr * 32 + m * 16 + gq;
        const size_t r1 = r0 + 8;
        const float rv00 = acc[m][n][0] + b0v, rv01 = acc[m][n][1] + b1v;
        const float rv10 = acc[m][n][2] + b0v, rv11 = acc[m][n][3] + b1v;
#pragma unroll
        for (int tt = 0; tt < 2; ++tt) {
          const int tb = tt ? tb1 : tb0;
          if (tb < 0) continue;
          const int xr = c_xrow[tb];
          const float2 x0 = *(const float2*)(xg + r0 * AW + xr * 128 + col);
          const float2 x1 = *(const float2*)(xg + r1 * AW + xr * 128 + col);
          __half2 h0 = __halves2half2(__float2half(x0.x * rv00),
                                      __float2half(x0.y * rv01));
          __half2 h1 = __halves2half2(__float2half(x1.x * rv10),
                                      __float2half(x1.y * rv11));
          *(__half2*)(g_Ahi + r0 * AW + tb * 128 + col) = h0;
          *(__half2*)(g_Ahi + r1 * AW + tb * 128 + col) = h1;
        }
      }
    }
    return;
  }

  // ---- normal epilogue ----
  const float* bp = (cfg.biasc >= 0) ? bias + cfg.biasc : nullptr;
#pragma unroll
  for (int m = 0; m < 2; ++m) {
#pragma unroll
    for (int n = 0; n < 8; ++n) {
      const int col = wc * 64 + n * 8 + tg * 2;
      float b0v = 0.f, b1v = 0.f;
      if (bp) { b0v = bp[col]; b1v = bp[col + 1]; }
      const size_t row = e0 + wr * 32 + m * 16 + gq;
      float* d0 = outp + row * (size_t)ostride + cfg.col0 + col;
      float* d1 = d0 + 8 * (size_t)ostride;
      *(float2*)d0 = make_float2(acc[m][n][0] + b0v, acc[m][n][1] + b1v);
      *(float2*)d1 = make_float2(acc[m][n][2] + b0v, acc[m][n][3] + b1v);
    }
  }
}

// ============================================================================
// Radial MLP layers 1+2 (fused LN+SiLU), SIMT; writes split-fp16 h2.
// ============================================================================
__device__ __forceinline__ void zero_acc8(float acc[4][8]) {
#pragma unroll
  for (int ee = 0; ee < 4; ++ee)
#pragma unroll
    for (int jj = 0; jj < 8; ++jj) acc[ee][jj] = 0.f;
}

__device__ __forceinline__ void rad_gemm128(const float* __restrict__ AT,
                                            const float* __restrict__ Wg,
                                            float* __restrict__ WS,
                                            float acc[4][8],
                                            int ty, int tx, int t)
{
  const int jL = t >> 1;
  const int kk0 = (t & 1) * 16;
  const float* wrow = Wg + jL * 128 + kk0;
#pragma unroll 1
  for (int kcu = 0; kcu < 4; ++kcu) {
#pragma unroll
    for (int u = 0; u < 4; ++u) {
      float4 v = *(const float4*)(wrow + kcu * 32 + u * 4);
      const int kk = kk0 + u * 4;
      WS[(kk + 0) * 132 + jL] = v.x;
      WS[(kk + 1) * 132 + jL] = v.y;
      WS[(kk + 2) * 132 + jL] = v.z;
      WS[(kk + 3) * 132 + jL] = v.w;
    }
    __syncthreads();
#pragma unroll
    for (int kk = 0; kk < 32; ++kk) {
      float4 a  = *(const float4*)(AT + (kcu * 32 + kk) * 68 + ty * 4);
      float4 b0 = *(const float4*)(WS + kk * 132 + tx * 8);
      float4 b1 = *(const float4*)(WS + kk * 132 + tx * 8 + 4);
      float av[4] = {a.x, a.y, a.z, a.w};
      float bv[8] = {b0.x, b0.y, b0.z, b0.w, b1.x, b1.y, b1.z, b1.w};
#pragma unroll
      for (int ee = 0; ee < 4; ++ee)
#pragma unroll
        for (int jj = 0; jj < 8; ++jj)
          acc[ee][jj] = fmaf(av[ee], bv[jj], acc[ee][jj]);
    }
    __syncthreads();
  }
}

__device__ __forceinline__ void store_bias_T(float* __restrict__ OT,
                                             const float acc[4][8],
                                             const float* __restrict__ bias,
                                             int ty, int tx)
{
  float4 q0 = *(const float4*)(bias + tx * 8);
  float4 q1 = *(const float4*)(bias + tx * 8 + 4);
  float bb[8] = {q0.x, q0.y, q0.z, q0.w, q1.x, q1.y, q1.z, q1.w};
#pragma unroll
  for (int jj = 0; jj < 8; ++jj) {
    const int j = tx * 8 + jj;
#pragma unroll
    for (int ee = 0; ee < 4; ++ee)
      OT[j * 68 + ty * 4 + ee] = acc[ee][jj] + bb[jj];
  }
}

__device__ __forceinline__ void ln_silu(float* __restrict__ HT,
                                        const float* __restrict__ g,
                                        const float* __restrict__ be, int t)
{
  const int e = t >> 2, q = t & 3;
  float vv[32];
  float s = 0.f, s2 = 0.f;
#pragma unroll
  for (int u = 0; u < 32; ++u) {
    float v = HT[(q * 32 + u) * 68 + e];
    vv[u] = v; s += v; s2 += v * v;
  }
  s  += __shfl_xor_sync(0xffffffffu, s, 1);
  s2 += __shfl_xor_sync(0xffffffffu, s2, 1);
  s  += __shfl_xor_sync(0xffffffffu, s, 2);
  s2 += __shfl_xor_sync(0xffffffffu, s2, 2);
  const float mu  = s * (1.0f / 128.0f);
  const float var = fmaf(-mu, mu, s2 * (1.0f / 128.0f));
  const float rin = rsqrtf(var + 1e-5f);
#pragma unroll
  for (int u = 0; u < 32; ++u) {
    const int j = q * 32 + u;
    float v = (vv[u] - mu) * rin * g[j] + be[j];
    v = v / (1.0f + expf(-v));
    HT[j * 68 + e] = v;
  }
}

__global__ __launch_bounds__(256)
void radial12_kernel(const float* __restrict__ xe,
                     const float* __restrict__ w1, const float* __restrict__ b1,
                     const float* __restrict__ g1, const float* __restrict__ be1,
                     const float* __restrict__ w2, const float* __restrict__ b2,
                     const float* __restrict__ g2, const float* __restrict__ be2)
{
  extern __shared__ float smx[];
  float* HA = smx;
  float* HB = smx + 128 * 68;
  float* WS = smx + 2 * 128 * 68;
  const int t = threadIdx.x;
  const int ty = t >> 4, tx = t & 15;
  const size_t e0 = (size_t)blockIdx.x * 64;

  {
    const int e = t >> 2, q = t & 3;
    const float* src = xe + (e0 + e) * 128 + q * 32;
#pragma unroll
    for (int u = 0; u < 8; ++u) {
      float4 v = *(const float4*)(src + u * 4);
      const int k = q * 32 + u * 4;
      HA[(k + 0) * 68 + e] = v.x;
      HA[(k + 1) * 68 + e] = v.y;
      HA[(k + 2) * 68 + e] = v.z;
      HA[(k + 3) * 68 + e] = v.w;
    }
  }
  __syncthreads();

  float acc[4][8];
  zero_acc8(acc);
  rad_gemm128(HA, w1, WS, acc, ty, tx, t);
  store_bias_T(HB, acc, b1, ty, tx);
  __syncthreads();
  ln_silu(HB, g1, be1, t);
  __syncthreads();

  zero_acc8(acc);
  rad_gemm128(HB, w2, WS, acc, ty, tx, t);
  store_bias_T(HA, acc, b2, ty, tx);
  __syncthreads();
  ln_silu(HA, g2, be2, t);

  // write split h2 (same thread wrote these elements in ln_silu -> no sync)
  {
    const int e = t >> 2, q = t & 3;
    __half* dh = g_h2hi + (e0 + e) * 128 + q * 32;
    __half* dl = g_h2lo + (e0 + e) * 128 + q * 32;
#pragma unroll
    for (int u = 0; u < 32; u += 2) {
      float v0 = HA[(q * 32 + u) * 68 + e];
      float v1 = HA[(q * 32 + u + 1) * 68 + e];
      __half h0, l0, h1, l1;
      split2(v0, h0, l0);
      split2(v1, h1, l1);
      *(__half2*)(dh + u) = __halves2half2(h0, h1);
      *(__half2*)(dl + u) = __halves2half2(l0, l1);
    }
  }
}

// ============================================================================
// single fused weight-split kernel (all 4 segments)
// ============================================================================
__global__ void convsplit_all(const float* __restrict__ fc0w,
                              const float* __restrict__ fc1w,
                              const float* __restrict__ fc2w,
                              const float* __restrict__ rw3)
{
  int i = blockIdx.x * 256 + threadIdx.x;
  if (i >= W_TOT) return;
  float v;
  if (i < W_FC1)      v = fc0w[i];
  else if (i < W_FC2) v = fc1w[i - W_FC1];
  else if (i < W_W3)  v = fc2w[i - W_FC2];
  else                v = rw3[i - W_W3];
  __half h, l;
  split2(v, h, l);
  g_Whi[i] = h;
  g_Wlo[i] = l;
}

// ---------------------------------------------------------------------------
extern "C" void kernel_launch(void* const* d_in, const int* in_sizes, int n_in,
                              void* d_out, int out_size)
{
  const float* x    = (const float*)d_in[0];
  const float* xe   = (const float*)d_in[1];
  const float* fc0w = (const float*)d_in[2];
  const float* fc0b = (const float*)d_in[3];
  const float* fc1w = (const float*)d_in[4];
  const float* fc2w = (const float*)d_in[5];
  const float* rw1  = (const float*)d_in[6];
  const float* rb1  = (const float*)d_in[7];
  const float* rg1  = (const float*)d_in[8];
  const float* rbe1 = (const float*)d_in[9];
  const float* rw2  = (const float*)d_in[10];
  const float* rb2  = (const float*)d_in[11];
  const float* rg2  = (const float*)d_in[12];
  const float* rbe2 = (const float*)d_in[13];
  const float* rw3  = (const float*)d_in[14];
  const float* rb3  = (const float*)d_in[15];
  float* out = (float*)d_out;

  const int N = in_sizes[1] / CH;
  const int nb64  = N / 64;
  const int nb128 = N / 128;

  // launch 1: all weight conversions
  convsplit_all<<<(W_TOT + 255) / 256, 256>>>(fc0w, fc1w, fc2w, rw3);

  // launch 2: radial layers 1+2 (SIMT, fused LN+SiLU) -> split h2
  const int smem_r = (2 * 128 * 68 + 32 * 132) * 4;
  cudaFuncSetAttribute(radial12_kernel,
                       cudaFuncAttributeMaxDynamicSharedMemorySize, smem_r);
  radial12_kernel<<<nb64, 256, smem_r>>>(xe, rw1, rb1, rg1, rbe1,
                                         rw2, rb2, rg2, rbe2);

  cudaFuncSetAttribute(mma_gemm,
                       cudaFuncAttributeMaxDynamicSharedMemorySize, SMEM_G);

  // launch 3: radial layer 3 GEMM (3-term) + fused FiLM/gather -> g_Ahi
  mma_gemm<<<dim3(12, nb128), 256, SMEM_G>>>(1, rb3, x, nullptr, 0, 19);

  // launch 4: all 19 SO2 output blocks in one launch (1-term, K=64 chunks)
  mma_gemm<<<dim3(19, nb128), 256, SMEM_G>>>(0, fc0b, nullptr, out, KC * CH, 0);
}

// round 16
// speedup vs baseline: 1.0509x; 1.0509x over previous
#include <cuda_runtime.h>
#include <cuda_fp16.h>
#include <cstdint>

static constexpr int NE_MAX = 32768;
static constexpr int KC = 19;
static constexpr int CH = 128;
static constexpr int AW = 2432;

// weight segment offsets inside g_Whi (elements)
static constexpr int W_FC0 = 0;                 // 640*640
static constexpr int W_FC1 = 409600;            // 512*512
static constexpr int W_FC2 = 671744;            // 384*384
static constexpr int W_W3  = 819200;            // 1536*128
static constexpr int W_TOT = 1015808;

// ------------------------- device scratch (no allocs allowed) ---------------
__device__ __align__(16) __half g_h2hi[(size_t)NE_MAX * CH];
__device__ __align__(16) __half g_h2lo[(size_t)NE_MAX * CH];
__device__ __align__(16) __half g_Ahi[(size_t)NE_MAX * AW];
__device__ __align__(16) __half g_Whi[W_TOT];

// A-block -> x source row (m-major expanded layout)
__constant__ int c_xrow[19] = {0,2,6,11,16, 3,7,12,17, 1,5,10,15, 8,13,18, 4,9,14};

// per-output-block GEMM config
struct Cfg { int acol0, K, wrow, col0, biasc, p0, p1, p2; };
__constant__ Cfg c_cfg[31] = {
  // --- SO2: fc0 (m=0), K=640, bias ---
  {0,    640, 0,      0,    0,   0,0,0},
  {0,    640, 81920,  256,  128, 0,0,0},
  {0,    640, 163840, 768,  256, 0,0,0},
  {0,    640, 245760, 1408, 384, 0,0,0},
  {0,    640, 327680, 2048, 512, 0,0,0},
  // --- fc1, +m rows {3,7,12,17} ---
  {640,  512, 409600, 384,  -1, 0,0,0},
  {640,  512, 475136, 896,  -1, 0,0,0},
  {640,  512, 540672, 1536, -1, 0,0,0},
  {640,  512, 606208, 2176, -1, 0,0,0},
  // --- fc1, -m rows {1,5,10,15} ---
  {1152, 512, 409600, 128,  -1, 0,0,0},
  {1152, 512, 475136, 640,  -1, 0,0,0},
  {1152, 512, 540672, 1280, -1, 0,0,0},
  {1152, 512, 606208, 1920, -1, 0,0,0},
  // --- fc2, +m rows {8,13,18} ---
  {1664, 384, 671744, 1024, -1, 0,0,0},
  {1664, 384, 720896, 1664, -1, 0,0,0},
  {1664, 384, 770048, 2304, -1, 0,0,0},
  // --- fc2, -m rows {4,9,14} ---
  {2048, 384, 671744, 512,  -1, 0,0,0},
  {2048, 384, 720896, 1152, -1, 0,0,0},
  {2048, 384, 770048, 1792, -1, 0,0,0},
  // --- w3 (radial layer 3), 12 blocks, K=128, bias=rb3, fused FiLM+split ---
  {0, 128, 819200,  0,    0,    0,0,0},
  {0, 128, 835584,  128,  128,  0,0,0},
  {0, 128, 851968,  256,  256,  0,0,0},
  {0, 128, 868352,  384,  384,  0,0,0},
  {0, 128, 884736,  512,  512,  0,0,0},
  {0, 128, 901120,  640,  640,  0,0,0},
  {0, 128, 917504,  768,  768,  0,0,0},
  {0, 128, 933888,  896,  896,  0,0,0},
  {0, 128, 950272,  1024, 1024, 0,0,0},
  {0, 128, 966656,  1152, 1152, 0,0,0},
  {0, 128, 983040,  1280, 1280, 0,0,0},
  {0, 128, 999424,  1408, 1408, 0,0,0},
};

// ------------------------- helpers ------------------------------------------
__device__ __forceinline__ uint32_t smem_u32(const void* p) {
  uint32_t a;
  asm("{ .reg .u64 t; cvta.to.shared.u64 t, %1; cvt.u32.u64 %0, t; }"
      : "=r"(a) : "l"(p));
  return a;
}
__device__ __forceinline__ void cp16(uint32_t dst, const void* src) {
  asm volatile("cp.async.cg.shared.global [%0], [%1], 16;" :: "r"(dst), "l"(src));
}
__device__ __forceinline__ void cp_commit() {
  asm volatile("cp.async.commit_group;");
}
__device__ __forceinline__ void cp_wait0() {
  asm volatile("cp.async.wait_group 0;" ::: "memory");
}
__device__ __forceinline__ void ldsm4(uint32_t* r, uint32_t a) {
  asm volatile("ldmatrix.sync.aligned.m8n8.x4.shared.b16 {%0,%1,%2,%3}, [%4];"
               : "=r"(r[0]), "=r"(r[1]), "=r"(r[2]), "=r"(r[3]) : "r"(a));
}
__device__ __forceinline__ void mma16816(float* c, const uint32_t* a,
                                         uint32_t b0, uint32_t b1) {
  asm volatile(
      "mma.sync.aligned.m16n8k16.row.col.f32.f16.f16.f32 "
      "{%0,%1,%2,%3}, {%4,%5,%6,%7}, {%8,%9}, {%0,%1,%2,%3};"
      : "+f"(c[0]), "+f"(c[1]), "+f"(c[2]), "+f"(c[3])
      : "r"(a[0]), "r"(a[1]), "r"(a[2]), "r"(a[3]), "r"(b0), "r"(b1));
}
__device__ __forceinline__ void split2(float v, __half& h, __half& l) {
  h = __float2half(v);
  l = __float2half(v - __half2float(h));
}

// smem per buffer: AH 0, AL 10240, WH 20480; [128 rows][32 k] fp16,
// row pitch 40 elems (80 B). (R14 layout kept; Wl plane removed.)
static constexpr int T_AL = 10240, T_WH = 20480;
static constexpr int BUFB = 40960;
static constexpr int SMEM_G = 2 * BUFB;   // 81920

// ============================================================================
// Unified GEMM (fp16 operands, fp32 accum):
//   mode 0 (SO2): D = Ah@Wh          (1 term; quant err ~2.9e-4 measured)
//   mode 1 (w3):  D = Ah@Wh + Al@Wh  (2 terms; rad err = W-quant ~2e-4), then
//                 fused epilogue: rad = D + bias; A = x_gather*rad -> fp16.
// cp.async staging, ldmatrix fragments, term-major order.
// 256 threads, 2 CTAs/SM, warp tile 32x64, M=128 CTA tile (R14 base config).
// ============================================================================
struct GemmCtx {
  const __half *gah, *gal, *gwh;
  uint32_t sdst, sb;
  int arow, akoff, brow0, bkoff;
};

template <int TERMS>
__device__ __forceinline__ void stage_chunk(const GemmCtx& c, int kc, uint32_t bo) {
  const __half* p;
  p = c.gah + kc * 32; cp16(c.sdst + bo, p);          cp16(c.sdst + bo + 16, p + 8);
  p = c.gwh + kc * 32; cp16(c.sdst + bo + T_WH, p);   cp16(c.sdst + bo + T_WH + 16, p + 8);
  if (TERMS == 2) {
    p = c.gal + kc * 32; cp16(c.sdst + bo + T_AL, p); cp16(c.sdst + bo + T_AL + 16, p + 8);
  }
}

template <int TERMS>
__device__ __forceinline__ void compute_chunk(const GemmCtx& c, uint32_t bo,
                                              float acc[2][8][4]) {
#pragma unroll
  for (int ks = 0; ks < 2; ++ks) {
    uint32_t Ah[2][4], Al[2][4];
#pragma unroll
    for (int m = 0; m < 2; ++m) {
      const uint32_t aa =
          c.sb + bo + (uint32_t)(c.arow + m * 16) * 80 + c.akoff + ks * 32;
      ldsm4(Ah[m], aa);
      if (TERMS == 2) ldsm4(Al[m], aa + T_AL);
    }
#pragma unroll
    for (int n2 = 0; n2 < 4; ++n2) {
      const uint32_t ba =
          c.sb + bo + T_WH + (uint32_t)(c.brow0 + n2 * 16) * 80 + c.bkoff + ks * 32;
      uint32_t Bh[4];
      ldsm4(Bh, ba);
      // term 1: Ah * Bh
      mma16816(acc[0][2 * n2],     Ah[0], Bh[0], Bh[1]);
      mma16816(acc[1][2 * n2],     Ah[1], Bh[0], Bh[1]);
      mma16816(acc[0][2 * n2 + 1], Ah[0], Bh[2], Bh[3]);
      mma16816(acc[1][2 * n2 + 1], Ah[1], Bh[2], Bh[3]);
      if (TERMS == 2) {
        // term 2: Al * Bh
        mma16816(acc[0][2 * n2],     Al[0], Bh[0], Bh[1]);
        mma16816(acc[1][2 * n2],     Al[1], Bh[0], Bh[1]);
        mma16816(acc[0][2 * n2 + 1], Al[0], Bh[2], Bh[3]);
        mma16816(acc[1][2 * n2 + 1], Al[1], Bh[2], Bh[3]);
      }
    }
  }
}

template <int NCH, int TERMS>
__device__ __forceinline__ void gemm_loop(const GemmCtx& c, float acc[2][8][4]) {
  stage_chunk<TERMS>(c, 0, 0);
  cp_commit();
  cp_wait0();
  __syncthreads();
#pragma unroll
  for (int kc = 0; kc < NCH; ++kc) {
    const uint32_t bo = (uint32_t)(kc & 1) * BUFB;
    if (kc + 1 < NCH) {
      stage_chunk<TERMS>(c, kc + 1, bo ^ BUFB);
      cp_commit();
    }
    compute_chunk<TERMS>(c, bo, acc);
    if (kc + 1 < NCH) {
      cp_wait0();
      __syncthreads();
    }
  }
}

__global__ void __launch_bounds__(256, 2)
mma_gemm(int mode, const float* __restrict__ bias,
         const float* __restrict__ xg,
         float* __restrict__ outp, int ostride, int cfg0)
{
  extern __shared__ char sm[];
  const Cfg cfg = c_cfg[cfg0 + blockIdx.x];
  const int K = cfg.K;
  const int t = threadIdx.x;
  const size_t e0 = (size_t)blockIdx.y * 128;

  // device-side A operand selection (device symbols invalid from host!)
  const __half* __restrict__ Ahi = (mode == 1) ? g_h2hi : g_Ahi;
  const __half* __restrict__ Alo = (mode == 1) ? g_h2lo : g_Ahi;  // unused mode0
  const int astride = (mode == 1) ? 128 : AW;

  GemmCtx c;
  c.sb = smem_u32(sm);

  // ---- staging mapping: 2 threads per row, 32 B (16 elems) per thread ----
  const int srow = t >> 1, sh = t & 1;
  c.gah = Ahi + (e0 + srow) * (size_t)astride + cfg.acol0 + sh * 16;
  c.gal = Alo + (e0 + srow) * (size_t)astride + cfg.acol0 + sh * 16;
  c.gwh = g_Whi + cfg.wrow + (size_t)srow * K + sh * 16;
  c.sdst = c.sb + srow * 80 + sh * 32;

  // ---- compute mapping: 8 warps as 4 (rows) x 2 (cols); tile 32x64 ----
  const int wid = t >> 5, lane = t & 31;
  const int wr = wid & 3, wc = wid >> 2;
  const int lm = lane >> 3, lr = lane & 7;        // ldmatrix matrix id, row
  c.arow  = wr * 32 + ((lm & 1) ? 8 : 0) + lr;
  c.akoff = (lm & 2) ? 16 : 0;
  c.brow0 = wc * 64 + ((lm & 2) ? 8 : 0) + lr;
  c.bkoff = (lm & 1) ? 16 : 0;
  const int gq = lane >> 2, tg = lane & 3;

  float acc[2][8][4];
#pragma unroll
  for (int m = 0; m < 2; ++m)
#pragma unroll
    for (int n = 0; n < 8; ++n)
#pragma unroll
      for (int u = 0; u < 4; ++u) acc[m][n][u] = 0.f;

  if (mode == 1) {
    gemm_loop<4, 2>(c, acc);          // w3: K=128, 2 terms (rad err ~2e-4)
  } else {
    switch (K >> 5) {                 // SO2: 1 term
      case 12: gemm_loop<12, 1>(c, acc); break;
      case 16: gemm_loop<16, 1>(c, acc); break;
      default: gemm_loop<20, 1>(c, acc); break;
    }
  }

  if (mode == 1) {
    // ---- fused epilogue: rad = D + bias; A = x_gather * rad -> fp16 ----
    const int jb = blockIdx.x;                    // 0..11 rad block
    int tb0, tb1;
    if (jb < 5)      { tb0 = jb;     tb1 = -1;     }   // m = 0
    else if (jb < 9) { tb0 = jb;     tb1 = jb + 4; }   // m = 1 (+m, -m)
    else             { tb0 = jb + 4; tb1 = jb + 7; }   // m = 2 (+m, -m)
    const float* bp = bias + cfg.biasc;
#pragma unroll
    for (int m = 0; m < 2; ++m) {
#pragma unroll
      for (int n = 0; n < 8; ++n) {
        const int col = wc * 64 + n * 8 + tg * 2;
        const float b0v = bp[col], b1v = bp[col + 1];
        const size_t r0 = e0 + wr * 32 + m * 16 + gq;
        const size_t r1 = r0 + 8;
        const float rv00 = acc[m][n][0] + b0v, rv01 = acc[m][n][1] + b1v;
        const float rv10 = acc[m][n][2] + b0v, rv11 = acc[m][n][3] + b1v;
#pragma unroll
        for (int tt = 0; tt < 2; ++tt) {
          const int tb = tt ? tb1 : tb0;
          if (tb < 0) continue;
          const int xr = c_xrow[tb];
          const float2 x0 = *(const float2*)(xg + r0 * AW + xr * 128 + col);
          const float2 x1 = *(const float2*)(xg + r1 * AW + xr * 128 + col);
          __half2 h0 = __halves2half2(__float2half(x0.x * rv00),
                                      __float2half(x0.y * rv01));
          __half2 h1 = __halves2half2(__float2half(x1.x * rv10),
                                      __float2half(x1.y * rv11));
          *(__half2*)(g_Ahi + r0 * AW + tb * 128 + col) = h0;
          *(__half2*)(g_Ahi + r1 * AW + tb * 128 + col) = h1;
        }
      }
    }
    return;
  }

  // ---- normal epilogue ----
  const float* bp = (cfg.biasc >= 0) ? bias + cfg.biasc : nullptr;
#pragma unroll
  for (int m = 0; m < 2; ++m) {
#pragma unroll
    for (int n = 0; n < 8; ++n) {
      const int col = wc * 64 + n * 8 + tg * 2;
      float b0v = 0.f, b1v = 0.f;
      if (bp) { b0v = bp[col]; b1v = bp[col + 1]; }
      const size_t row = e0 + wr * 32 + m * 16 + gq;
      float* d0 = outp + row * (size_t)ostride + cfg.col0 + col;
      float* d1 = d0 + 8 * (size_t)ostride;
      *(float2*)d0 = make_float2(acc[m][n][0] + b0v, acc[m][n][1] + b1v);
      *(float2*)d1 = make_float2(acc[m][n][2] + b0v, acc[m][n][3] + b1v);
    }
  }
}

// ============================================================================
// Radial MLP layers 1+2 (fused LN+SiLU), SIMT; writes split-fp16 h2.
// ============================================================================
__device__ __forceinline__ void zero_acc8(float acc[4][8]) {
#pragma unroll
  for (int ee = 0; ee < 4; ++ee)
#pragma unroll
    for (int jj = 0; jj < 8; ++jj) acc[ee][jj] = 0.f;
}

__device__ __forceinline__ void rad_gemm128(const float* __restrict__ AT,
                                            const float* __restrict__ Wg,
                                            float* __restrict__ WS,
                                            float acc[4][8],
                                            int ty, int tx, int t)
{
  const int jL = t >> 1;
  const int kk0 = (t & 1) * 16;
  const float* wrow = Wg + jL * 128 + kk0;
#pragma unroll 1
  for (int kcu = 0; kcu < 4; ++kcu) {
#pragma unroll
    for (int u = 0; u < 4; ++u) {
      float4 v = *(const float4*)(wrow + kcu * 32 + u * 4);
      const int kk = kk0 + u * 4;
      WS[(kk + 0) * 132 + jL] = v.x;
      WS[(kk + 1) * 132 + jL] = v.y;
      WS[(kk + 2) * 132 + jL] = v.z;
      WS[(kk + 3) * 132 + jL] = v.w;
    }
    __syncthreads();
#pragma unroll
    for (int kk = 0; kk < 32; ++kk) {
      float4 a  = *(const float4*)(AT + (kcu * 32 + kk) * 68 + ty * 4);
      float4 b0 = *(const float4*)(WS + kk * 132 + tx * 8);
      float4 b1 = *(const float4*)(WS + kk * 132 + tx * 8 + 4);
      float av[4] = {a.x, a.y, a.z, a.w};
      float bv[8] = {b0.x, b0.y, b0.z, b0.w, b1.x, b1.y, b1.z, b1.w};
#pragma unroll
      for (int ee = 0; ee < 4; ++ee)
#pragma unroll
        for (int jj = 0; jj < 8; ++jj)
          acc[ee][jj] = fmaf(av[ee], bv[jj], acc[ee][jj]);
    }
    __syncthreads();
  }
}

__device__ __forceinline__ void store_bias_T(float* __restrict__ OT,
                                             const float acc[4][8],
                                             const float* __restrict__ bias,
                                             int ty, int tx)
{
  float4 q0 = *(const float4*)(bias + tx * 8);
  float4 q1 = *(const float4*)(bias + tx * 8 + 4);
  float bb[8] = {q0.x, q0.y, q0.z, q0.w, q1.x, q1.y, q1.z, q1.w};
#pragma unroll
  for (int jj = 0; jj < 8; ++jj) {
    const int j = tx * 8 + jj;
#pragma unroll
    for (int ee = 0; ee < 4; ++ee)
      OT[j * 68 + ty * 4 + ee] = acc[ee][jj] + bb[jj];
  }
}

__device__ __forceinline__ void ln_silu(float* __restrict__ HT,
                                        const float* __restrict__ g,
                                        const float* __restrict__ be, int t)
{
  const int e = t >> 2, q = t & 3;
  float vv[32];
  float s = 0.f, s2 = 0.f;
#pragma unroll
  for (int u = 0; u < 32; ++u) {
    float v = HT[(q * 32 + u) * 68 + e];
    vv[u] = v; s += v; s2 += v * v;
  }
  s  += __shfl_xor_sync(0xffffffffu, s, 1);
  s2 += __shfl_xor_sync(0xffffffffu, s2, 1);
  s  += __shfl_xor_sync(0xffffffffu, s, 2);
  s2 += __shfl_xor_sync(0xffffffffu, s2, 2);
  const float mu  = s * (1.0f / 128.0f);
  const float var = fmaf(-mu, mu, s2 * (1.0f / 128.0f));
  const float rin = rsqrtf(var + 1e-5f);
#pragma unroll
  for (int u = 0; u < 32; ++u) {
    const int j = q * 32 + u;
    float v = (vv[u] - mu) * rin * g[j] + be[j];
    v = v / (1.0f + expf(-v));
    HT[j * 68 + e] = v;
  }
}

__global__ __launch_bounds__(256)
void radial12_kernel(const float* __restrict__ xe,
                     const float* __restrict__ w1, const float* __restrict__ b1,
                     const float* __restrict__ g1, const float* __restrict__ be1,
                     const float* __restrict__ w2, const float* __restrict__ b2,
                     const float* __restrict__ g2, const float* __restrict__ be2)
{
  extern __shared__ float smx[];
  float* HA = smx;
  float* HB = smx + 128 * 68;
  float* WS = smx + 2 * 128 * 68;
  const int t = threadIdx.x;
  const int ty = t >> 4, tx = t & 15;
  const size_t e0 = (size_t)blockIdx.x * 64;

  {
    const int e = t >> 2, q = t & 3;
    const float* src = xe + (e0 + e) * 128 + q * 32;
#pragma unroll
    for (int u = 0; u < 8; ++u) {
      float4 v = *(const float4*)(src + u * 4);
      const int k = q * 32 + u * 4;
      HA[(k + 0) * 68 + e] = v.x;
      HA[(k + 1) * 68 + e] = v.y;
      HA[(k + 2) * 68 + e] = v.z;
      HA[(k + 3) * 68 + e] = v.w;
    }
  }
  __syncthreads();

  float acc[4][8];
  zero_acc8(acc);
  rad_gemm128(HA, w1, WS, acc, ty, tx, t);
  store_bias_T(HB, acc, b1, ty, tx);
  __syncthreads();
  ln_silu(HB, g1, be1, t);
  __syncthreads();

  zero_acc8(acc);
  rad_gemm128(HB, w2, WS, acc, ty, tx, t);
  store_bias_T(HA, acc, b2, ty, tx);
  __syncthreads();
  ln_silu(HA, g2, be2, t);

  // write split h2 (same thread wrote these elements in ln_silu -> no sync)
  {
    const int e = t >> 2, q = t & 3;
    __half* dh = g_h2hi + (e0 + e) * 128 + q * 32;
    __half* dl = g_h2lo + (e0 + e) * 128 + q * 32;
#pragma unroll
    for (int u = 0; u < 32; u += 2) {
      float v0 = HA[(q * 32 + u) * 68 + e];
      float v1 = HA[(q * 32 + u + 1) * 68 + e];
      __half h0, l0, h1, l1;
      split2(v0, h0, l0);
      split2(v1, h1, l1);
      *(__half2*)(dh + u) = __halves2half2(h0, h1);
      *(__half2*)(dl + u) = __halves2half2(l0, l1);
    }
  }
}

// ============================================================================
// single fused weight conversion kernel (hi plane only; Wl no longer used)
// ============================================================================
__global__ void convsplit_all(const float* __restrict__ fc0w,
                              const float* __restrict__ fc1w,
                              const float* __restrict__ fc2w,
                              const float* __restrict__ rw3)
{
  int i = blockIdx.x * 256 + threadIdx.x;
  if (i >= W_TOT) return;
  float v;
  if (i < W_FC1)      v = fc0w[i];
  else if (i < W_FC2) v = fc1w[i - W_FC1];
  else if (i < W_W3)  v = fc2w[i - W_FC2];
  else                v = rw3[i - W_W3];
  g_Whi[i] = __float2half(v);
}

// ---------------------------------------------------------------------------
extern "C" void kernel_launch(void* const* d_in, const int* in_sizes, int n_in,
                              void* d_out, int out_size)
{
  const float* x    = (const float*)d_in[0];
  const float* xe   = (const float*)d_in[1];
  const float* fc0w = (const float*)d_in[2];
  const float* fc0b = (const float*)d_in[3];
  const float* fc1w = (const float*)d_in[4];
  const float* fc2w = (const float*)d_in[5];
  const float* rw1  = (const float*)d_in[6];
  const float* rb1  = (const float*)d_in[7];
  const float* rg1  = (const float*)d_in[8];
  const float* rbe1 = (const float*)d_in[9];
  const float* rw2  = (const float*)d_in[10];
  const float* rb2  = (const float*)d_in[11];
  const float* rg2  = (const float*)d_in[12];
  const float* rbe2 = (const float*)d_in[13];
  const float* rw3  = (const float*)d_in[14];
  const float* rb3  = (const float*)d_in[15];
  float* out = (float*)d_out;

  const int N = in_sizes[1] / CH;
  const int nb64  = N / 64;
  const int nb128 = N / 128;

  // launch 1: weight conversion (fp16 hi plane)
  convsplit_all<<<(W_TOT + 255) / 256, 256>>>(fc0w, fc1w, fc2w, rw3);

  // launch 2: radial layers 1+2 (SIMT, fused LN+SiLU) -> split h2
  const int smem_r = (2 * 128 * 68 + 32 * 132) * 4;
  cudaFuncSetAttribute(radial12_kernel,
                       cudaFuncAttributeMaxDynamicSharedMemorySize, smem_r);
  radial12_kernel<<<nb64, 256, smem_r>>>(xe, rw1, rb1, rg1, rbe1,
                                         rw2, rb2, rg2, rbe2);

  cudaFuncSetAttribute(mma_gemm,
                       cudaFuncAttributeMaxDynamicSharedMemorySize, SMEM_G);

  // launch 3: radial layer 3 GEMM (2-term) + fused FiLM/gather -> g_Ahi
  mma_gemm<<<dim3(12, nb128), 256, SMEM_G>>>(1, rb3, x, nullptr, 0, 19);

  // launch 4: all 19 SO2 output blocks in one launch (1-term fp16)
  mma_gemm<<<dim3(19, nb128), 256, SMEM_G>>>(0, fc0b, nullptr, out, KC * CH, 0);
}